// round 4
// baseline (speedup 1.0000x reference)
#include <cuda_runtime.h>
#include <mma.h>
#include <cstdint>
#include <math.h>
using namespace nvcuda;

#define BATCH 64
#define C 128
#define HW 3136
#define KSPLIT 2
#define KPART 1568
#define NCHUNK 49       // KPART/32
#define NUM_ITER 5
#define TRIU 8256
#define XLD 36          // smem ld for SYRK chunk (mult of 4, padded)
#define MLD 132         // smem ld for NS matrices

__device__ float g_G[KSPLIT][BATCH][C][C];
__device__ float g_s[KSPLIT][BATCH][C];

__device__ __forceinline__ float rtf32(float f) {
    uint32_t u; asm("cvt.rna.tf32.f32 %0, %1;" : "=r"(u) : "f"(f));
    return __uint_as_float(u);
}

typedef wmma::fragment<wmma::accumulator, 16, 16, 8, float> AccFrag;
typedef wmma::fragment<wmma::matrix_a, 16, 16, 8, wmma::precision::tf32, wmma::row_major> AFrag;
typedef wmma::fragment<wmma::matrix_b, 16, 16, 8, wmma::precision::tf32, wmma::col_major> BFrag;

// Per-warp upper-triangular tile config (8x8 frag grid of 16x16 frags)
__device__ __forceinline__ void warp_cfg(int w, int& rb, int& rn, int& cb, int& cn) {
    rb = (w == 0) ? 0 : (w == 1) ? 4 : (w == 2) ? 0 : 2;
    rn = (w < 2) ? 4 : 2;
    cb = (w == 0) ? 0 : 4;
    cn = 4;
}

// ===================== Kernel 1: SYRK via wmma tf32 =========================
// grid (KSPLIT, BATCH), 128 threads. Upper-triangular frag tiles + mirror.
__global__ __launch_bounds__(128, 1)
void syrk_tc(const float* __restrict__ x) {
    __shared__ __align__(16) float Xs[2][128 * XLD];
    const int ks = blockIdx.x, b = blockIdx.y;
    const int t = threadIdx.x, w = t >> 5;
    const float* xb = x + (size_t)b * C * HW + (size_t)ks * KPART;

    int rb, rn, cb, cn;
    warp_cfg(w, rb, rn, cb, cn);

    AccFrag acc[4][4];
#pragma unroll
    for (int i = 0; i < 4; i++)
#pragma unroll
        for (int j = 0; j < 4; j++) wmma::fill_fragment(acc[i][j], 0.0f);

    const int rbase = t >> 3;   // 0..15
    const int seg = t & 7;      // 0..7
    float4 R[8], Rn[8];
    float rs[8];
#pragma unroll
    for (int i = 0; i < 8; i++) rs[i] = 0.0f;

#pragma unroll
    for (int i = 0; i < 8; i++)
        R[i] = *(const float4*)(xb + (size_t)(rbase + i * 16) * HW + seg * 4);

    for (int c = 0; c < NCHUNK; c++) {
        float* buf = Xs[c & 1];
#pragma unroll
        for (int i = 0; i < 8; i++) {
            float4 v = R[i];
            rs[i] += v.x + v.y + v.z + v.w;
            float* p = buf + (rbase + i * 16) * XLD + seg * 4;
            p[0] = rtf32(v.x); p[1] = rtf32(v.y); p[2] = rtf32(v.z); p[3] = rtf32(v.w);
        }
        if (c + 1 < NCHUNK) {
            const float* xc = xb + (c + 1) * 32 + seg * 4;
#pragma unroll
            for (int i = 0; i < 8; i++)
                Rn[i] = *(const float4*)(xc + (size_t)(rbase + i * 16) * HW);
        }
        __syncthreads();

#pragma unroll
        for (int kk = 0; kk < 4; kk++) {
            AFrag a[4];
            BFrag bf[4];
#pragma unroll
            for (int i = 0; i < 4; i++)
                if (i < rn) wmma::load_matrix_sync(a[i], buf + ((rb + i) * 16) * XLD + kk * 8, XLD);
#pragma unroll
            for (int j = 0; j < 4; j++)
                if (j < cn) wmma::load_matrix_sync(bf[j], buf + ((cb + j) * 16) * XLD + kk * 8, XLD);
#pragma unroll
            for (int i = 0; i < 4; i++)
#pragma unroll
                for (int j = 0; j < 4; j++)
                    if (i < rn && j < cn && (cb + j) >= (rb + i))
                        wmma::mma_sync(acc[i][j], a[i], bf[j], acc[i][j]);
        }
#pragma unroll
        for (int i = 0; i < 8; i++) R[i] = Rn[i];
    }

    // store Gram (upper + mirrored lower)
    float* Gp = &g_G[ks][b][0][0];
#pragma unroll
    for (int i = 0; i < 4; i++)
#pragma unroll
        for (int j = 0; j < 4; j++)
            if (i < rn && j < cn && (cb + j) >= (rb + i)) {
                wmma::store_matrix_sync(Gp + (rb + i) * 16 * C + (cb + j) * 16,
                                        acc[i][j], C, wmma::mem_row_major);
                if ((cb + j) > (rb + i))
                    wmma::store_matrix_sync(Gp + (cb + j) * 16 * C + (rb + i) * 16,
                                            acc[i][j], C, wmma::mem_col_major);
            }

    // row sums: reduce across the 8 seg-lanes sharing a row group
#pragma unroll
    for (int i = 0; i < 8; i++) {
        rs[i] += __shfl_xor_sync(0xffffffffu, rs[i], 1);
        rs[i] += __shfl_xor_sync(0xffffffffu, rs[i], 2);
        rs[i] += __shfl_xor_sync(0xffffffffu, rs[i], 4);
    }
    if (seg == 0) {
#pragma unroll
        for (int i = 0; i < 8; i++) g_s[ks][b][rbase + i * 16] = rs[i];
    }
}

// ===================== NS GEMM: split-tf32 (fp32 accurate) ==================
__device__ __forceinline__ void ns_gemm(const float* __restrict__ A, const float* __restrict__ Bm,
                                        float* __restrict__ D,
                                        int rb, int rn, int cb, int cn,
                                        bool mirror, bool presync) {
    AccFrag acc[4][4];
#pragma unroll
    for (int i = 0; i < 4; i++)
#pragma unroll
        for (int j = 0; j < 4; j++) wmma::fill_fragment(acc[i][j], 0.0f);

    for (int k = 0; k < C; k += 8) {
        AFrag ah[4], al[4];
#pragma unroll
        for (int i = 0; i < 4; i++)
            if (i < rn) {
                wmma::load_matrix_sync(al[i], A + (rb + i) * 16 * MLD + k, MLD);
#pragma unroll
                for (int e = 0; e < al[i].num_elements; e++) {
                    float v = al[i].x[e];
                    float h = rtf32(v);
                    ah[i].x[e] = h;
                    al[i].x[e] = v - h;
                }
            }
#pragma unroll
        for (int j = 0; j < 4; j++)
            if (j < cn) {
                BFrag bh, bl;
                wmma::load_matrix_sync(bl, Bm + (cb + j) * 16 * MLD + k, MLD);
#pragma unroll
                for (int e = 0; e < bl.num_elements; e++) {
                    float v = bl.x[e];
                    float h = rtf32(v);
                    bh.x[e] = h;
                    bl.x[e] = v - h;
                }
#pragma unroll
                for (int i = 0; i < 4; i++)
                    if (i < rn && (cb + j) >= (rb + i)) {
                        wmma::mma_sync(acc[i][j], ah[i], bh, acc[i][j]);
                        wmma::mma_sync(acc[i][j], ah[i], bl, acc[i][j]);
                        wmma::mma_sync(acc[i][j], al[i], bh, acc[i][j]);
                    }
            }
    }
    if (presync) __syncthreads();
#pragma unroll
    for (int i = 0; i < 4; i++)
#pragma unroll
        for (int j = 0; j < 4; j++)
            if (i < rn && j < cn && (cb + j) >= (rb + i)) {
                wmma::store_matrix_sync(D + (rb + i) * 16 * MLD + (cb + j) * 16,
                                        acc[i][j], MLD, wmma::mem_row_major);
                if (mirror && (cb + j) > (rb + i))
                    wmma::store_matrix_sync(D + (cb + j) * 16 * MLD + (rb + i) * 16,
                                            acc[i][j], MLD, wmma::mem_col_major);
            }
}

// ===================== Kernel 2: fused Newton-Schulz ========================
// grid (BATCH), 128 threads, ~203KB dynamic smem. Y/Z/T fp32, symmetric.
#define NS_SMEM_FLOATS (3 * 128 * MLD + 128 + 32)

__global__ __launch_bounds__(128, 1)
void ns_tc(float* __restrict__ out) {
    extern __shared__ __align__(16) float sm[];
    float* Y = sm;
    float* Z = Y + 128 * MLD;
    float* T = Z + 128 * MLD;
    float* mu = T + 128 * MLD;
    float* red = mu + 128;

    const int b = blockIdx.x;
    const int t = threadIdx.x, w = t >> 5, lane = t & 31;
    int rb, rn, cb, cn;
    warp_cfg(w, rb, rn, cb, cn);

    const float invn = 1.0f / (float)HW;
    const float* G0 = &g_G[0][b][0][0];
    const float* G1 = &g_G[1][b][0][0];

    const float m = (g_s[0][b][t] + g_s[1][b][t]) * invn;
    mu[t] = m;
    float d = (G0[t * C + t] + G1[t * C + t]) * invn - m * m;
#pragma unroll
    for (int o = 16; o; o >>= 1) d += __shfl_down_sync(0xffffffffu, d, o);
    if (lane == 0) red[w] = d;
    __syncthreads();
    const float tr = red[0] + red[1] + red[2] + red[3];
    const float invtr = 1.0f / tr;

    for (int e = t; e < C * C; e += 128) {
        const int i = e >> 7, j = e & 127;
        const float g = G0[e] + G1[e];
        Y[i * MLD + j] = (g * invn - mu[i] * mu[j]) * invtr;
        Z[i * MLD + j] = (i == j) ? 1.0f : 0.0f;
    }
    __syncthreads();

    for (int it = 0; it < NUM_ITER; it++) {
        // D0 = Z@Y -> T   (T free; no presync needed)
        ns_gemm(Z, Y, T, rb, rn, cb, cn, true, false);
        __syncthreads();
        // T = 1.5 I - 0.5 T (in place, row t per thread)
        {
            float* row = T + t * MLD;
#pragma unroll 8
            for (int j = 0; j < C; j++) {
                const float v = row[j];
                row[j] = fmaf(-0.5f, v, (j == t) ? 1.5f : 0.0f);
            }
        }
        __syncthreads();

        if (it < NUM_ITER - 1) {
            // D1 = Y@T -> Y (presync: all reads of Y done before overwrite)
            ns_gemm(Y, T, Y, rb, rn, cb, cn, true, true);
            // D2 = T@Z -> Z
            ns_gemm(T, Z, Z, rb, rn, cb, cn, true, true);
            __syncthreads();
        } else {
            ns_gemm(Y, T, Y, rb, rn, cb, cn, false, true);
            __syncthreads();
        }
    }

    // Output: triu(Y * sqrt(tr))
    const float s = sqrtf(tr);
    const int i = t;
    float* o = out + (size_t)b * TRIU + i * (257 - i) / 2;
    const float* yr = Y + i * MLD;
    for (int j = i; j < C; j++) o[j - i] = yr[j] * s;
}

// =================== launch ==================================================
extern "C" void kernel_launch(void* const* d_in, const int* in_sizes, int n_in,
                              void* d_out, int out_size) {
    const float* x = (const float*)d_in[0];
    float* out = (float*)d_out;
    cudaFuncSetAttribute(ns_tc, cudaFuncAttributeMaxDynamicSharedMemorySize,
                         NS_SMEM_FLOATS * (int)sizeof(float));
    dim3 g1(KSPLIT, BATCH);
    syrk_tc<<<g1, 128>>>(x);
    ns_tc<<<BATCH, 128, NS_SMEM_FLOATS * sizeof(float)>>>(out);
}